// round 3
// baseline (speedup 1.0000x reference)
#include <cuda_runtime.h>
#include <cuda_bf16.h>
#include <math.h>

// ---------------- constants ----------------
#define Bb 16
#define Ls 511
#define Ss 512
#define Dd 1024
#define HIDh 512
#define DFFf 2048
#define EAe 256
#define NHh 4
#define HDh 256   // D/NH

#define BM 128
#define BN 128
#define BKk 8
#define TM 8
#define TN 8
#define BMP 132   // padded

// ---------------- scratch (static device memory; no allocation) ----------------
__device__ float d_h   [8192L*1024];
__device__ float d_mem [8192L*1024];
__device__ float d_qkv [8192L*3072];
__device__ float d_att [64L*512*512];
__device__ float d_x1  [8192L*2048];
__device__ float d_x2  [8192L*1024];

// ---------------- generic SGEMM: C = act(alpha * A @ op(B) + bias) ----------------
// A row-major [M,K] (lda), TB=1: B is [N,K] (ldb, use B^T); TB=0: B is [K,N] (ldb).
// Batched via blockIdx.z with (b,h) decomposition: z -> bb=z/nh, hh=z%nh.
// Requires: M%128==0, N%128==0, K%8==0, lda/ldb/ldc %4==0, all base ptrs 16B aligned.
template<int TB, int ACT>
__global__ __launch_bounds__(256) void gemm_k(
    const float* __restrict__ A, const float* __restrict__ B,
    const float* __restrict__ bias, float* __restrict__ C,
    int M, int N, int K, int lda, int ldb, int ldc,
    long sAb, long sAh, long sBb, long sBh, long sCb, long sCh, int nh,
    float alpha)
{
    int z = blockIdx.z;
    int bb = z / nh, hh = z % nh;
    A += bb * sAb + hh * sAh;
    B += bb * sBb + hh * sBh;
    C += bb * sCb + hh * sCh;

    __shared__ float As[BKk][BMP];
    __shared__ float Bs[BKk][BMP];

    int tid = threadIdx.x;
    int m0 = blockIdx.y * BM;
    int n0 = blockIdx.x * BN;

    int arow = tid >> 1;
    int acol = (tid & 1) * 4;
    int brow, bcol;
    if (TB) { brow = tid >> 1; bcol = (tid & 1) * 4; }
    else    { brow = tid >> 5; bcol = (tid & 31) * 4; }

    int ty = tid >> 4;
    int tx = tid & 15;
    int rowB = ty * TM;
    int colB = tx * TN;

    float acc[TM][TN];
    #pragma unroll
    for (int i = 0; i < TM; i++)
        #pragma unroll
        for (int j = 0; j < TN; j++) acc[i][j] = 0.f;

    for (int k0 = 0; k0 < K; k0 += BKk) {
        float4 av = *reinterpret_cast<const float4*>(&A[(long)(m0 + arow) * lda + k0 + acol]);
        As[acol + 0][arow] = av.x; As[acol + 1][arow] = av.y;
        As[acol + 2][arow] = av.z; As[acol + 3][arow] = av.w;
        if (TB) {
            float4 bv = *reinterpret_cast<const float4*>(&B[(long)(n0 + brow) * ldb + k0 + bcol]);
            Bs[bcol + 0][brow] = bv.x; Bs[bcol + 1][brow] = bv.y;
            Bs[bcol + 2][brow] = bv.z; Bs[bcol + 3][brow] = bv.w;
        } else {
            float4 bv = *reinterpret_cast<const float4*>(&B[(long)(k0 + brow) * ldb + n0 + bcol]);
            *reinterpret_cast<float4*>(&Bs[brow][bcol]) = bv;
        }
        __syncthreads();
        #pragma unroll
        for (int k = 0; k < BKk; k++) {
            float a[TM], b[TN];
            #pragma unroll
            for (int i = 0; i < TM; i++) a[i] = As[k][rowB + i];
            #pragma unroll
            for (int j = 0; j < TN; j++) b[j] = Bs[k][colB + j];
            #pragma unroll
            for (int i = 0; i < TM; i++)
                #pragma unroll
                for (int j = 0; j < TN; j++) acc[i][j] += a[i] * b[j];
        }
        __syncthreads();
    }

    #pragma unroll
    for (int i = 0; i < TM; i++) {
        long crow = (long)(m0 + rowB + i) * ldc + n0;
        #pragma unroll
        for (int j = 0; j < TN; j += 4) {
            float4 v;
            float* vp = &v.x;
            #pragma unroll
            for (int q = 0; q < 4; q++) {
                float x = acc[i][j + q] * alpha;
                if (bias) x += bias[n0 + colB + j + q];
                if (ACT == 1) x = fmaxf(x, 0.f);
                if (ACT == 2) x = (x >= 0.f) ? x : 0.01f * x;
                vp[q] = x;
            }
            *reinterpret_cast<float4*>(&C[crow + colB + j]) = v;
        }
    }
}

// ---------------- softmax (in place, optional causal) ----------------
__global__ void softmax_k(float* __restrict__ att, int causal)
{
    int q = blockIdx.x;
    int z = blockIdx.y;
    float* p = att + ((long)z * Ss + q) * Ss;
    int len = causal ? (q + 1) : Ss;
    __shared__ float sh[256];
    int tid = threadIdx.x;

    float mx = -1e30f;
    for (int i = tid; i < len; i += 256) mx = fmaxf(mx, p[i]);
    sh[tid] = mx; __syncthreads();
    for (int s = 128; s > 0; s >>= 1) { if (tid < s) sh[tid] = fmaxf(sh[tid], sh[tid + s]); __syncthreads(); }
    mx = sh[0]; __syncthreads();

    float sum = 0.f;
    for (int i = tid; i < len; i += 256) { float e = __expf(p[i] - mx); p[i] = e; sum += e; }
    sh[tid] = sum; __syncthreads();
    for (int s = 128; s > 0; s >>= 1) { if (tid < s) sh[tid] += sh[tid + s]; __syncthreads(); }
    float inv = 1.f / sh[0];

    for (int i = tid; i < len; i += 256) p[i] *= inv;
    for (int i = len + tid; i < Ss; i += 256) p[i] = 0.f;
}

// ---------------- h = LN(h + delta) ----------------
__global__ void ln_add_k(float* __restrict__ h, const float* __restrict__ d,
                         const float* __restrict__ w, const float* __restrict__ b)
{
    long row = blockIdx.x;
    float* x = h + row * Dd;
    const float* dd = d + row * Dd;
    int tid = threadIdx.x;
    __shared__ float sh[256];

    float v[4];
    float s = 0.f;
    #pragma unroll
    for (int t = 0; t < 4; t++) { int i = tid + t * 256; v[t] = x[i] + dd[i]; s += v[t]; }
    sh[tid] = s; __syncthreads();
    for (int st = 128; st > 0; st >>= 1) { if (tid < st) sh[tid] += sh[tid + st]; __syncthreads(); }
    float mean = sh[0] * (1.f / Dd); __syncthreads();

    float s2 = 0.f;
    #pragma unroll
    for (int t = 0; t < 4; t++) { float u = v[t] - mean; s2 += u * u; }
    sh[tid] = s2; __syncthreads();
    for (int st = 128; st > 0; st >>= 1) { if (tid < st) sh[tid] += sh[tid + st]; __syncthreads(); }
    float rstd = rsqrtf(sh[0] * (1.f / Dd) + 1e-5f);

    #pragma unroll
    for (int t = 0; t < 4; t++) { int i = tid + t * 256; x[i] = (v[t] - mean) * rstd * w[i] + b[i]; }
}

// ---------------- input projection stage 1: leaky(t*w1 + b1) ----------------
__global__ void build1_k(const float* __restrict__ tgtn, const float* __restrict__ bos,
                         const float* __restrict__ w1, const float* __restrict__ b1,
                         float* __restrict__ out)
{
    long idx = (long)blockIdx.x * 256 + threadIdx.x;   // B*S*HID
    long row = idx >> 9;
    int j = (int)(idx & 511);
    int bb = (int)(row >> 9);
    int s = (int)(row & 511);
    float t = (s == 0) ? bos[0] : tgtn[bb * Ls + s - 1];
    float v = t * w1[j] + b1[j];
    out[idx] = (v >= 0.f) ? v : 0.01f * v;
}

// ---------------- assemble tgt(+PE) and mem ----------------
__global__ void build2_k(const float* __restrict__ x2, const float* __restrict__ gs,
                         const float* __restrict__ prev, const float* __restrict__ cur,
                         float* __restrict__ tgt, float* __restrict__ mem)
{
    int row = blockIdx.x;
    int bb = row >> 9;
    int s = row & 511;
    long ob = (long)row * Dd;
    for (int i = threadIdx.x; i < Dd; i += 256) {
        float tv, mv;
        if (i < HIDh) {
            int jj = i & ~1;
            float div = __expf((float)jj * (-9.210340371976184f / 512.f));
            double ang = (double)s * (double)div;
            double r = ang - 6.283185307179586 * rint(ang * 0.15915494309189535);
            float fr = (float)r;
            float pe = (i & 1) ? cosf(fr) : sinf(fr);
            tv = x2[(long)row * HIDh + i] + pe;
            mv = gs[(long)row * HIDh + i];
        } else if (i < HIDh + EAe) {
            float a = prev[bb * EAe + (i - HIDh)];
            tv = a; mv = a;
        } else {
            float a = cur[bb * EAe + (i - HIDh - EAe)];
            tv = a; mv = a;
        }
        tgt[ob + i] = tv;
        mem[ob + i] = mv;
    }
}

// ---------------- final: y2 = y1 @ w2^T + b2, masked by basis_dim ----------------
__global__ void final_k(const float* __restrict__ y1, const float* __restrict__ w2,
                        const float* __restrict__ b2, const int* __restrict__ basis,
                        float* __restrict__ out)
{
    int idx = blockIdx.x * 8 + (threadIdx.x >> 5);
    if (idx >= Bb * Ls) return;
    int bb = idx / Ls, l = idx % Ls;
    const float* r = y1 + ((long)bb * Ss + l + 1) * HIDh;
    int lane = threadIdx.x & 31;
    float s = 0.f;
    for (int j = lane; j < HIDh; j += 32) s += r[j] * w2[j];
    #pragma unroll
    for (int o = 16; o; o >>= 1) s += __shfl_xor_sync(0xffffffffu, s, o);
    if (lane == 0) out[idx] = (l < basis[bb]) ? (s + b2[0]) : 0.f;
}

// ---------------- host-side helpers ----------------
static void gemm(int TB, int ACT,
                 const float* A, const float* B, const float* bias, float* C,
                 int M, int N, int K, int lda, int ldb, int ldc,
                 long sAb, long sAh, long sBb, long sBh, long sCb, long sCh,
                 int nb, int nh, float alpha)
{
    dim3 grid(N / BN, M / BM, nb * nh);
#define GCALL(tb, act) gemm_k<tb, act><<<grid, 256>>>(A, B, bias, C, M, N, K, lda, ldb, ldc, sAb, sAh, sBb, sBh, sCb, sCh, nh, alpha)
    if (TB) {
        if (ACT == 0) GCALL(1, 0);
        else if (ACT == 1) GCALL(1, 1);
        else GCALL(1, 2);
    } else {
        GCALL(0, 0);
    }
#undef GCALL
}

extern "C" void kernel_launch(void* const* d_in, const int* in_sizes, int n_in,
                              void* d_out, int out_size)
{
    const float* gs      = (const float*)d_in[0];
    const float* prev    = (const float*)d_in[1];
    const float* cur     = (const float*)d_in[2];
    const float* tgtn    = (const float*)d_in[3];
    const float* bos     = (const float*)d_in[4];
    const float* inp_w1  = (const float*)d_in[5];
    const float* inp_b1  = (const float*)d_in[6];
    const float* inp_w2  = (const float*)d_in[7];
    const float* inp_b2  = (const float*)d_in[8];
    const float* sa_qkv_w= (const float*)d_in[9];
    const float* sa_qkv_b= (const float*)d_in[10];
    const float* sa_out_w= (const float*)d_in[11];
    const float* sa_out_b= (const float*)d_in[12];
    const float* ca_qkv_w= (const float*)d_in[13];
    const float* ca_qkv_b= (const float*)d_in[14];
    const float* ca_out_w= (const float*)d_in[15];
    const float* ca_out_b= (const float*)d_in[16];
    const float* ln_w    = (const float*)d_in[17];
    const float* ln_b    = (const float*)d_in[18];
    const float* ff_w1   = (const float*)d_in[19];
    const float* ff_b1   = (const float*)d_in[20];
    const float* ff_w2   = (const float*)d_in[21];
    const float* ff_b2   = (const float*)d_in[22];
    const float* proj_w1 = (const float*)d_in[23];
    const float* proj_b1 = (const float*)d_in[24];
    const float* proj_w2 = (const float*)d_in[25];
    const float* proj_b2 = (const float*)d_in[26];
    const int*   basis   = (const int*)d_in[27];

    float *h, *mem, *qkv, *att, *x1, *x2;
    cudaGetSymbolAddress((void**)&h,   d_h);
    cudaGetSymbolAddress((void**)&mem, d_mem);
    cudaGetSymbolAddress((void**)&qkv, d_qkv);
    cudaGetSymbolAddress((void**)&att, d_att);
    cudaGetSymbolAddress((void**)&x1,  d_x1);
    cudaGetSymbolAddress((void**)&x2,  d_x2);

    const int M = Bb * Ss;          // 8192
    const long zero = 0;

    // ---- build tgt & mem ----
    build1_k<<<(M * HIDh) / 256, 256>>>(tgtn, bos, inp_w1, inp_b1, x1);
    gemm(1, 0, x1, inp_w2, inp_b2, x2, M, HIDh, HIDh, HIDh, HIDh, HIDh,
         zero, zero, zero, zero, zero, zero, 1, 1, 1.f);
    build2_k<<<M, 256>>>(x2, gs, prev, cur, h, mem);

    const long sTok  = (long)Ss * 3072;      // per-batch stride in qkv buffer
    const long sAttB = (long)NHh * Ss * Ss;
    const long sAttH = (long)Ss * Ss;
    const float iscale = 1.f / 16.f;         // 1/sqrt(hd)

    for (int l = 0; l < 3; l++) {
        // ===== self-attention =====
        gemm(1, 0, h, sa_qkv_w + (long)l * 3 * Dd * Dd, sa_qkv_b + (long)l * 3 * Dd, qkv,
             M, 3 * Dd, Dd, Dd, Dd, 3 * Dd, zero, zero, zero, zero, zero, zero, 1, 1, 1.f);
        // scores = Q @ K^T * iscale
        gemm(1, 0, qkv, qkv + Dd, nullptr, att, Ss, Ss, HDh, 3 * Dd, 3 * Dd, Ss,
             sTok, (long)HDh, sTok, (long)HDh, sAttB, sAttH, Bb, NHh, iscale);
        softmax_k<<<dim3(Ss, Bb * NHh), 256>>>(att, 1);
        // O = P @ V
        gemm(0, 0, att, qkv + 2 * Dd, nullptr, x1, Ss, HDh, Ss, Ss, 3 * Dd, Dd,
             sAttB, sAttH, sTok, (long)HDh, (long)Ss * Dd, (long)HDh, Bb, NHh, 1.f);
        gemm(1, 0, x1, sa_out_w + (long)l * Dd * Dd, sa_out_b + (long)l * Dd, x2,
             M, Dd, Dd, Dd, Dd, Dd, zero, zero, zero, zero, zero, zero, 1, 1, 1.f);
        ln_add_k<<<M, 256>>>(h, x2, ln_w + (long)(l * 3 + 0) * Dd, ln_b + (long)(l * 3 + 0) * Dd);

        // ===== cross-attention =====
        gemm(1, 0, h, ca_qkv_w + (long)l * 3 * Dd * Dd, ca_qkv_b + (long)l * 3 * Dd, qkv,
             M, Dd, Dd, Dd, Dd, 3 * Dd, zero, zero, zero, zero, zero, zero, 1, 1, 1.f);
        gemm(1, 0, mem, ca_qkv_w + (long)l * 3 * Dd * Dd + (long)Dd * Dd,
             ca_qkv_b + (long)l * 3 * Dd + Dd, qkv + Dd,
             M, 2 * Dd, Dd, Dd, Dd, 3 * Dd, zero, zero, zero, zero, zero, zero, 1, 1, 1.f);
        gemm(1, 0, qkv, qkv + Dd, nullptr, att, Ss, Ss, HDh, 3 * Dd, 3 * Dd, Ss,
             sTok, (long)HDh, sTok, (long)HDh, sAttB, sAttH, Bb, NHh, iscale);
        softmax_k<<<dim3(Ss, Bb * NHh), 256>>>(att, 0);
        gemm(0, 0, att, qkv + 2 * Dd, nullptr, x1, Ss, HDh, Ss, Ss, 3 * Dd, Dd,
             sAttB, sAttH, sTok, (long)HDh, (long)Ss * Dd, (long)HDh, Bb, NHh, 1.f);
        gemm(1, 0, x1, ca_out_w + (long)l * Dd * Dd, ca_out_b + (long)l * Dd, x2,
             M, Dd, Dd, Dd, Dd, Dd, zero, zero, zero, zero, zero, zero, 1, 1, 1.f);
        ln_add_k<<<M, 256>>>(h, x2, ln_w + (long)(l * 3 + 1) * Dd, ln_b + (long)(l * 3 + 1) * Dd);

        // ===== feed-forward =====
        gemm(1, 1, h, ff_w1 + (long)l * DFFf * Dd, ff_b1 + (long)l * DFFf, x1,
             M, DFFf, Dd, Dd, Dd, DFFf, zero, zero, zero, zero, zero, zero, 1, 1, 1.f);
        gemm(1, 0, x1, ff_w2 + (long)l * Dd * DFFf, ff_b2 + (long)l * Dd, x2,
             M, Dd, DFFf, DFFf, DFFf, Dd, zero, zero, zero, zero, zero, zero, 1, 1, 1.f);
        ln_add_k<<<M, 256>>>(h, x2, ln_w + (long)(l * 3 + 2) * Dd, ln_b + (long)(l * 3 + 2) * Dd);
    }

    // ---- output head ----
    gemm(1, 2, h, proj_w1, proj_b1, x1, M, HIDh, Dd, Dd, Dd, HIDh,
         zero, zero, zero, zero, zero, zero, 1, 1, 1.f);
    final_k<<<(Bb * Ls + 7) / 8, 256>>>(x1, proj_w2, proj_b2, basis, (float*)d_out);
}

// round 5
// speedup vs baseline: 3.0590x; 3.0590x over previous
#include <cuda_runtime.h>
#include <math.h>
#include <stdint.h>

// ---------------- problem constants ----------------
#define Bb 16
#define Ls 511
#define Ss 512
#define Dd 1024
#define HIDh 512
#define DFFf 2048
#define EAe 256
#define NHh 4
#define HDh 256   // D/NH

// ---------------- scratch (static device memory) ----------------
__device__ float d_h   [8192L*1024];
__device__ float d_mem [8192L*1024];
__device__ float d_qkv [8192L*3072];
__device__ float d_att [64L*512*512];
__device__ float d_x1  [8192L*2048];
__device__ float d_x2  [8192L*1024];

// ---------------- mma.sync helpers ----------------
__device__ __forceinline__ uint32_t f2tf(float x) {
    uint32_t u;
    asm("cvt.rna.tf32.f32 %0, %1;" : "=r"(u) : "f"(x));
    return u;
}

__device__ __forceinline__ void mma8(float* c, const uint32_t* a, const uint32_t* b) {
    asm volatile(
        "mma.sync.aligned.m16n8k8.row.col.f32.tf32.tf32.f32 "
        "{%0,%1,%2,%3}, {%4,%5,%6,%7}, {%8,%9}, {%0,%1,%2,%3};"
        : "+f"(c[0]), "+f"(c[1]), "+f"(c[2]), "+f"(c[3])
        : "r"(a[0]), "r"(a[1]), "r"(a[2]), "r"(a[3]), "r"(b[0]), "r"(b[1]));
}

__device__ __forceinline__ void cpa(uint32_t d, const float* s) {
    asm volatile("cp.async.cg.shared.global [%0], [%1], 16;" :: "r"(d), "l"(s));
}

// ---------------- tf32 tensor-core GEMM: C = act(alpha * A @ op(B) + bias) ----------
// CTA tile 128x256, warp tile 64x64 (2x4 warps), BK=32, 3-stage cp.async pipeline.
// TB=1: B is [N,K] row-major; TB=0: B is [K,N]. Batched via blockIdx.z -> (bb,hh).
// Requires M%128==0, N%256==0, K%32==0, all leading dims %4, bases 16B-aligned.
template<int TB, int ACT>
__global__ void __launch_bounds__(256, 1)
mma_gemm_k(const float* __restrict__ A, const float* __restrict__ B,
           const float* __restrict__ bias, float* __restrict__ C,
           int K, int lda, int ldb, int ldc,
           long sAb, long sAh, long sBb, long sBh, long sCb, long sCh,
           int nh, float alpha)
{
    constexpr int AP = 36;                 // A smem row pitch (floats)
    constexpr int BP = TB ? 36 : 264;      // B smem row pitch (floats)
    constexpr int AE = 128 * AP;           // A floats per stage
    constexpr int BE = TB ? 256 * BP : 32 * BP;
    constexpr int STG = AE + BE;           // floats per stage

    extern __shared__ float smem[];

    int tid = threadIdx.x;
    int wid = tid >> 5, lane = tid & 31;
    int gq = lane >> 2, gr = lane & 3;     // groupID / thread-in-group
    int wm0 = (wid >> 2) * 64;             // warp m offset in CTA tile
    int wn0 = (wid & 3) * 64;              // warp n offset

    int z = blockIdx.z, bb = z / nh, hh = z - bb * nh;
    A += bb * sAb + hh * sAh;
    B += bb * sBb + hh * sBh;
    C += bb * sCb + hh * sCh;
    int m0 = blockIdx.y * 128, n0 = blockIdx.x * 256;

    float acc[4][8][4];
    #pragma unroll
    for (int i = 0; i < 4; i++)
        #pragma unroll
        for (int j = 0; j < 8; j++)
            #pragma unroll
            for (int q = 0; q < 4; q++) acc[i][j][q] = 0.f;

    auto ldst = [&](int s, int k0) {
        uint32_t base = (uint32_t)__cvta_generic_to_shared(smem + s * STG);
        const float* Ag = A + (long)m0 * lda + k0;
        #pragma unroll
        for (int i = 0; i < 4; i++) {
            int ch = tid + 256 * i;
            int row = ch >> 3, c = ch & 7;
            cpa(base + (uint32_t)(row * AP + c * 4) * 4, Ag + (long)row * lda + c * 4);
        }
        uint32_t bbase = base + AE * 4;
        if (TB) {
            const float* Bg = B + (long)n0 * ldb + k0;
            #pragma unroll
            for (int i = 0; i < 8; i++) {
                int ch = tid + 256 * i;
                int row = ch >> 3, c = ch & 7;
                cpa(bbase + (uint32_t)(row * BP + c * 4) * 4, Bg + (long)row * ldb + c * 4);
            }
        } else {
            const float* Bg = B + (long)k0 * ldb + n0;
            #pragma unroll
            for (int i = 0; i < 8; i++) {
                int ch = tid + 256 * i;
                int row = ch >> 6, c = ch & 63;
                cpa(bbase + (uint32_t)(row * BP + c * 4) * 4, Bg + (long)row * ldb + c * 4);
            }
        }
        asm volatile("cp.async.commit_group;" ::: "memory");
    };

    int nk = K / 32;
    ldst(0, 0);
    ldst(1, 32);

    for (int it = 0; it < nk; it++) {
        asm volatile("cp.async.wait_group 1;" ::: "memory");
        __syncthreads();
        if (it + 2 < nk) ldst((it + 2) % 3, (it + 2) * 32);
        else asm volatile("cp.async.commit_group;" ::: "memory");

        const float* As = smem + (it % 3) * STG;
        const float* Bs = As + AE;
        #pragma unroll
        for (int k8 = 0; k8 < 4; k8++) {
            uint32_t au[4][4];
            #pragma unroll
            for (int mi = 0; mi < 4; mi++) {
                int r = wm0 + mi * 16 + gq;
                int cc = k8 * 8 + gr;
                au[mi][0] = f2tf(As[r * AP + cc]);
                au[mi][1] = f2tf(As[(r + 8) * AP + cc]);
                au[mi][2] = f2tf(As[r * AP + cc + 4]);
                au[mi][3] = f2tf(As[(r + 8) * AP + cc + 4]);
            }
            uint32_t bu[8][2];
            #pragma unroll
            for (int ni = 0; ni < 8; ni++) {
                if (TB) {
                    int row = wn0 + ni * 8 + gq;
                    bu[ni][0] = f2tf(Bs[row * BP + k8 * 8 + gr]);
                    bu[ni][1] = f2tf(Bs[row * BP + k8 * 8 + gr + 4]);
                } else {
                    int col = wn0 + ni * 8 + gq;
                    bu[ni][0] = f2tf(Bs[(k8 * 8 + gr) * BP + col]);
                    bu[ni][1] = f2tf(Bs[(k8 * 8 + gr + 4) * BP + col]);
                }
            }
            #pragma unroll
            for (int mi = 0; mi < 4; mi++)
                #pragma unroll
                for (int ni = 0; ni < 8; ni++)
                    mma8(acc[mi][ni], au[mi], bu[ni]);
        }
    }

    // epilogue
    #pragma unroll
    for (int mi = 0; mi < 4; mi++) {
        int r0 = m0 + wm0 + mi * 16 + gq;
        #pragma unroll
        for (int ni = 0; ni < 8; ni++) {
            int c0 = n0 + wn0 + ni * 8 + gr * 2;
            float bz0 = 0.f, bz1 = 0.f;
            if (bias) { bz0 = bias[c0]; bz1 = bias[c0 + 1]; }
            float2 v;
            v.x = acc[mi][ni][0] * alpha + bz0;
            v.y = acc[mi][ni][1] * alpha + bz1;
            if (ACT == 1) { v.x = fmaxf(v.x, 0.f); v.y = fmaxf(v.y, 0.f); }
            if (ACT == 2) { v.x = (v.x >= 0.f) ? v.x : 0.01f * v.x; v.y = (v.y >= 0.f) ? v.y : 0.01f * v.y; }
            *reinterpret_cast<float2*>(&C[(long)r0 * ldc + c0]) = v;
            v.x = acc[mi][ni][2] * alpha + bz0;
            v.y = acc[mi][ni][3] * alpha + bz1;
            if (ACT == 1) { v.x = fmaxf(v.x, 0.f); v.y = fmaxf(v.y, 0.f); }
            if (ACT == 2) { v.x = (v.x >= 0.f) ? v.x : 0.01f * v.x; v.y = (v.y >= 0.f) ? v.y : 0.01f * v.y; }
            *reinterpret_cast<float2*>(&C[(long)(r0 + 8) * ldc + c0]) = v;
        }
    }
}

// ---------------- softmax (in place, optional causal) ----------------
__global__ void softmax_k(float* __restrict__ att, int causal)
{
    int q = blockIdx.x;
    int z = blockIdx.y;
    float* p = att + ((long)z * Ss + q) * Ss;
    int len = causal ? (q + 1) : Ss;
    __shared__ float sh[256];
    int tid = threadIdx.x;

    float mx = -1e30f;
    for (int i = tid; i < len; i += 256) mx = fmaxf(mx, p[i]);
    sh[tid] = mx; __syncthreads();
    for (int s = 128; s > 0; s >>= 1) { if (tid < s) sh[tid] = fmaxf(sh[tid], sh[tid + s]); __syncthreads(); }
    mx = sh[0]; __syncthreads();

    float sum = 0.f;
    for (int i = tid; i < len; i += 256) { float e = __expf(p[i] - mx); p[i] = e; sum += e; }
    sh[tid] = sum; __syncthreads();
    for (int s = 128; s > 0; s >>= 1) { if (tid < s) sh[tid] += sh[tid + s]; __syncthreads(); }
    float inv = 1.f / sh[0];

    for (int i = tid; i < len; i += 256) p[i] *= inv;
    for (int i = len + tid; i < Ss; i += 256) p[i] = 0.f;
}

// ---------------- h = LN(h + delta) ----------------
__global__ void ln_add_k(float* __restrict__ h, const float* __restrict__ d,
                         const float* __restrict__ w, const float* __restrict__ b)
{
    long row = blockIdx.x;
    float* x = h + row * Dd;
    const float* dd = d + row * Dd;
    int tid = threadIdx.x;
    __shared__ float sh[256];

    float v[4];
    float s = 0.f;
    #pragma unroll
    for (int t = 0; t < 4; t++) { int i = tid + t * 256; v[t] = x[i] + dd[i]; s += v[t]; }
    sh[tid] = s; __syncthreads();
    for (int st = 128; st > 0; st >>= 1) { if (tid < st) sh[tid] += sh[tid + st]; __syncthreads(); }
    float mean = sh[0] * (1.f / Dd); __syncthreads();

    float s2 = 0.f;
    #pragma unroll
    for (int t = 0; t < 4; t++) { float u = v[t] - mean; s2 += u * u; }
    sh[tid] = s2; __syncthreads();
    for (int st = 128; st > 0; st >>= 1) { if (tid < st) sh[tid] += sh[tid + st]; __syncthreads(); }
    float rstd = rsqrtf(sh[0] * (1.f / Dd) + 1e-5f);

    #pragma unroll
    for (int t = 0; t < 4; t++) { int i = tid + t * 256; x[i] = (v[t] - mean) * rstd * w[i] + b[i]; }
}

// ---------------- input projection stage 1: leaky(t*w1 + b1) ----------------
__global__ void build1_k(const float* __restrict__ tgtn, const float* __restrict__ bos,
                         const float* __restrict__ w1, const float* __restrict__ b1,
                         float* __restrict__ out)
{
    long idx = (long)blockIdx.x * 256 + threadIdx.x;
    long row = idx >> 9;
    int j = (int)(idx & 511);
    int bb = (int)(row >> 9);
    int s = (int)(row & 511);
    float t = (s == 0) ? bos[0] : tgtn[bb * Ls + s - 1];
    float v = t * w1[j] + b1[j];
    out[idx] = (v >= 0.f) ? v : 0.01f * v;
}

// ---------------- assemble tgt(+PE) and mem ----------------
__global__ void build2_k(const float* __restrict__ x2, const float* __restrict__ gs,
                         const float* __restrict__ prev, const float* __restrict__ cur,
                         float* __restrict__ tgt, float* __restrict__ mem)
{
    int row = blockIdx.x;
    int bb = row >> 9;
    int s = row & 511;
    long ob = (long)row * Dd;
    for (int i = threadIdx.x; i < Dd; i += 256) {
        float tv, mv;
        if (i < HIDh) {
            int jj = i & ~1;
            float div = __expf((float)jj * (-9.210340371976184f / 512.f));
            double ang = (double)s * (double)div;
            double r = ang - 6.283185307179586 * rint(ang * 0.15915494309189535);
            float fr = (float)r;
            float pe = (i & 1) ? cosf(fr) : sinf(fr);
            tv = x2[(long)row * HIDh + i] + pe;
            mv = gs[(long)row * HIDh + i];
        } else if (i < HIDh + EAe) {
            float a = prev[bb * EAe + (i - HIDh)];
            tv = a; mv = a;
        } else {
            float a = cur[bb * EAe + (i - HIDh - EAe)];
            tv = a; mv = a;
        }
        tgt[ob + i] = tv;
        mem[ob + i] = mv;
    }
}

// ---------------- final: y2 = y1 @ w2^T + b2, masked by basis_dim ----------------
__global__ void final_k(const float* __restrict__ y1, const float* __restrict__ w2,
                        const float* __restrict__ b2, const int* __restrict__ basis,
                        float* __restrict__ out)
{
    int idx = blockIdx.x * 8 + (threadIdx.x >> 5);
    if (idx >= Bb * Ls) return;
    int bb = idx / Ls, l = idx % Ls;
    const float* r = y1 + ((long)bb * Ss + l + 1) * HIDh;
    int lane = threadIdx.x & 31;
    float s = 0.f;
    for (int j = lane; j < HIDh; j += 32) s += r[j] * w2[j];
    #pragma unroll
    for (int o = 16; o; o >>= 1) s += __shfl_xor_sync(0xffffffffu, s, o);
    if (lane == 0) out[idx] = (l < basis[bb]) ? (s + b2[0]) : 0.f;
}

// ---------------- host-side launcher ----------------
#define SMEM_TB1 ((128*36 + 256*36) * 4 * 3)   // 165888
#define SMEM_TB0 ((128*36 + 32*264) * 4 * 3)   // 156672

static void tc_gemm(int TB, int ACT,
                    const float* A, const float* B, const float* bias, float* C,
                    int M, int N, int K, int lda, int ldb, int ldc,
                    long sAb, long sAh, long sBb, long sBh, long sCb, long sCh,
                    int nb, int nh, float alpha)
{
    dim3 grid(N / 256, M / 128, nb * nh);
#define TCALL(tb, act, sm) mma_gemm_k<tb, act><<<grid, 256, sm>>>( \
        A, B, bias, C, K, lda, ldb, ldc, sAb, sAh, sBb, sBh, sCb, sCh, nh, alpha)
    if (TB) {
        if (ACT == 0) TCALL(1, 0, SMEM_TB1);
        else if (ACT == 1) TCALL(1, 1, SMEM_TB1);
        else TCALL(1, 2, SMEM_TB1);
    } else {
        TCALL(0, 0, SMEM_TB0);
    }
#undef TCALL
}

extern "C" void kernel_launch(void* const* d_in, const int* in_sizes, int n_in,
                              void* d_out, int out_size)
{
    const float* gs      = (const float*)d_in[0];
    const float* prev    = (const float*)d_in[1];
    const float* cur     = (const float*)d_in[2];
    const float* tgtn    = (const float*)d_in[3];
    const float* bos     = (const float*)d_in[4];
    const float* inp_w1  = (const float*)d_in[5];
    const float* inp_b1  = (const float*)d_in[6];
    const float* inp_w2  = (const float*)d_in[7];
    const float* inp_b2  = (const float*)d_in[8];
    const float* sa_qkv_w= (const float*)d_in[9];
    const float* sa_qkv_b= (const float*)d_in[10];
    const float* sa_out_w= (const float*)d_in[11];
    const float* sa_out_b= (const float*)d_in[12];
    const float* ca_qkv_w= (const float*)d_in[13];
    const float* ca_qkv_b= (const float*)d_in[14];
    const float* ca_out_w= (const float*)d_in[15];
    const float* ca_out_b= (const float*)d_in[16];
    const float* ln_w    = (const float*)d_in[17];
    const float* ln_b    = (const float*)d_in[18];
    const float* ff_w1   = (const float*)d_in[19];
    const float* ff_b1   = (const float*)d_in[20];
    const float* ff_w2   = (const float*)d_in[21];
    const float* ff_b2   = (const float*)d_in[22];
    const float* proj_w1 = (const float*)d_in[23];
    const float* proj_b1 = (const float*)d_in[24];
    const float* proj_w2 = (const float*)d_in[25];
    const float* proj_b2 = (const float*)d_in[26];
    const int*   basis   = (const int*)d_in[27];

    // opt-in to large dynamic smem (host-side, capture-safe, idempotent)
    cudaFuncSetAttribute(mma_gemm_k<1, 0>, cudaFuncAttributeMaxDynamicSharedMemorySize, SMEM_TB1);
    cudaFuncSetAttribute(mma_gemm_k<1, 1>, cudaFuncAttributeMaxDynamicSharedMemorySize, SMEM_TB1);
    cudaFuncSetAttribute(mma_gemm_k<1, 2>, cudaFuncAttributeMaxDynamicSharedMemorySize, SMEM_TB1);
    cudaFuncSetAttribute(mma_gemm_k<0, 0>, cudaFuncAttributeMaxDynamicSharedMemorySize, SMEM_TB0);

    float *h, *mem, *qkv, *att, *x1, *x2;
    cudaGetSymbolAddress((void**)&h,   d_h);
    cudaGetSymbolAddress((void**)&mem, d_mem);
    cudaGetSymbolAddress((void**)&qkv, d_qkv);
    cudaGetSymbolAddress((void**)&att, d_att);
    cudaGetSymbolAddress((void**)&x1,  d_x1);
    cudaGetSymbolAddress((void**)&x2,  d_x2);

    const int M = Bb * Ss;          // 8192
    const long zero = 0;

    // ---- build tgt & mem ----
    build1_k<<<(M * HIDh) / 256, 256>>>(tgtn, bos, inp_w1, inp_b1, x1);
    tc_gemm(1, 0, x1, inp_w2, inp_b2, x2, M, HIDh, HIDh, HIDh, HIDh, HIDh,
            zero, zero, zero, zero, zero, zero, 1, 1, 1.f);
    build2_k<<<M, 256>>>(x2, gs, prev, cur, h, mem);

    const long sTok  = (long)Ss * 3072;
    const long sAttB = (long)NHh * Ss * Ss;
    const long sAttH = (long)Ss * Ss;
    const float iscale = 1.f / 16.f;         // 1/sqrt(hd)

    for (int l = 0; l < 3; l++) {
        // ===== self-attention =====
        tc_gemm(1, 0, h, sa_qkv_w + (long)l * 3 * Dd * Dd, sa_qkv_b + (long)l * 3 * Dd, qkv,
                M, 3 * Dd, Dd, Dd, Dd, 3 * Dd, zero, zero, zero, zero, zero, zero, 1, 1, 1.f);
        tc_gemm(1, 0, qkv, qkv + Dd, nullptr, att, Ss, Ss, HDh, 3 * Dd, 3 * Dd, Ss,
                sTok, (long)HDh, sTok, (long)HDh, sAttB, sAttH, Bb, NHh, iscale);
        softmax_k<<<dim3(Ss, Bb * NHh), 256>>>(att, 1);
        tc_gemm(0, 0, att, qkv + 2 * Dd, nullptr, x1, Ss, HDh, Ss, Ss, 3 * Dd, Dd,
                sAttB, sAttH, sTok, (long)HDh, (long)Ss * Dd, (long)HDh, Bb, NHh, 1.f);
        tc_gemm(1, 0, x1, sa_out_w + (long)l * Dd * Dd, sa_out_b + (long)l * Dd, x2,
                M, Dd, Dd, Dd, Dd, Dd, zero, zero, zero, zero, zero, zero, 1, 1, 1.f);
        ln_add_k<<<M, 256>>>(h, x2, ln_w + (long)(l * 3 + 0) * Dd, ln_b + (long)(l * 3 + 0) * Dd);

        // ===== cross-attention =====
        tc_gemm(1, 0, h, ca_qkv_w + (long)l * 3 * Dd * Dd, ca_qkv_b + (long)l * 3 * Dd, qkv,
                M, Dd, Dd, Dd, Dd, 3 * Dd, zero, zero, zero, zero, zero, zero, 1, 1, 1.f);
        tc_gemm(1, 0, mem, ca_qkv_w + (long)l * 3 * Dd * Dd + (long)Dd * Dd,
                ca_qkv_b + (long)l * 3 * Dd + Dd, qkv + Dd,
                M, 2 * Dd, Dd, Dd, Dd, 3 * Dd, zero, zero, zero, zero, zero, zero, 1, 1, 1.f);
        tc_gemm(1, 0, qkv, qkv + Dd, nullptr, att, Ss, Ss, HDh, 3 * Dd, 3 * Dd, Ss,
                sTok, (long)HDh, sTok, (long)HDh, sAttB, sAttH, Bb, NHh, iscale);
        softmax_k<<<dim3(Ss, Bb * NHh), 256>>>(att, 0);
        tc_gemm(0, 0, att, qkv + 2 * Dd, nullptr, x1, Ss, HDh, Ss, Ss, 3 * Dd, Dd,
                sAttB, sAttH, sTok, (long)HDh, (long)Ss * Dd, (long)HDh, Bb, NHh, 1.f);
        tc_gemm(1, 0, x1, ca_out_w + (long)l * Dd * Dd, ca_out_b + (long)l * Dd, x2,
                M, Dd, Dd, Dd, Dd, Dd, zero, zero, zero, zero, zero, zero, 1, 1, 1.f);
        ln_add_k<<<M, 256>>>(h, x2, ln_w + (long)(l * 3 + 1) * Dd, ln_b + (long)(l * 3 + 1) * Dd);

        // ===== feed-forward =====
        tc_gemm(1, 1, h, ff_w1 + (long)l * DFFf * Dd, ff_b1 + (long)l * DFFf, x1,
                M, DFFf, Dd, Dd, Dd, DFFf, zero, zero, zero, zero, zero, zero, 1, 1, 1.f);
        tc_gemm(1, 0, x1, ff_w2 + (long)l * Dd * DFFf, ff_b2 + (long)l * Dd, x2,
                M, Dd, DFFf, DFFf, DFFf, Dd, zero, zero, zero, zero, zero, zero, 1, 1, 1.f);
        ln_add_k<<<M, 256>>>(h, x2, ln_w + (long)(l * 3 + 2) * Dd, ln_b + (long)(l * 3 + 2) * Dd);
    }

    // ---- output head ----
    tc_gemm(1, 2, h, proj_w1, proj_b1, x1, M, HIDh, Dd, Dd, Dd, HIDh,
            zero, zero, zero, zero, zero, zero, 1, 1, 1.f);
    final_k<<<(Bb * Ls + 7) / 8, 256>>>(x1, proj_w2, proj_b2, basis, (float*)d_out);
}

// round 8
// speedup vs baseline: 4.0704x; 1.3306x over previous
#include <cuda_runtime.h>
#include <cuda_fp16.h>
#include <math.h>
#include <stdint.h>

// ---------------- problem constants ----------------
#define Bb 16
#define Ls 511
#define Ss 512
#define Dd 1024
#define HIDh 512
#define DFFf 2048
#define EAe 256
#define NHh 4
#define HDh 256   // D/NH

// ---------------- GEMM tile config ----------------
#define AP 40                     // A smem pitch (halves)
#define BP1 40                    // B smem pitch, TB=1
#define BP0 264                   // B smem pitch, TB=0
#define AE_H (128*AP)             // A halves per stage
#define STG1_H (AE_H + 256*BP1)   // 15360 halves
#define STG0_H (AE_H + 32*BP0)    // 13568 halves
#define SMEM_TB1 (STG1_H*2*4)     // 122880 B
#define SMEM_TB0 (STG0_H*2*4)     // 108544 B

// ---------------- scratch (static device memory) ----------------
__device__ float  d_h   [8192L*1024];
__device__ float  d_x2  [8192L*1024];
__device__ float  d_att [64L*512*512];
__device__ __half d_h16 [8192L*1024];
__device__ __half d_mem16[8192L*1024];
__device__ __half d_qkv16[8192L*3072];
__device__ __half d_att16[64L*512*512];
__device__ __half d_xh  [8192L*2048];
__device__ __half d_wh  [38535168];

// weight-region offsets in d_wh (halves)
#define W_SAQKV  0L
#define W_SAOUT  9437184L
#define W_CAQKV  12582912L
#define W_CAOUT  22020096L
#define W_FFW1   25165824L
#define W_FFW2   31457280L
#define W_INPW2  37748736L
#define W_PROJW1 38010880L

// ---------------- asm helpers ----------------
__device__ __forceinline__ void cpa(uint32_t d, const __half* s) {
    asm volatile("cp.async.cg.shared.global [%0], [%1], 16;" :: "r"(d), "l"(s));
}
#define LDSM4(r0,r1,r2,r3,a) \
    asm volatile("ldmatrix.sync.aligned.m8n8.x4.shared.b16 {%0,%1,%2,%3}, [%4];" \
                 : "=r"(r0),"=r"(r1),"=r"(r2),"=r"(r3) : "r"(a))
#define LDSM4T(r0,r1,r2,r3,a) \
    asm volatile("ldmatrix.sync.aligned.m8n8.x4.trans.shared.b16 {%0,%1,%2,%3}, [%4];" \
                 : "=r"(r0),"=r"(r1),"=r"(r2),"=r"(r3) : "r"(a))

__device__ __forceinline__ void mma16(float* c, const uint32_t* a, const uint32_t* b) {
    asm volatile(
        "mma.sync.aligned.m16n8k16.row.col.f32.f16.f16.f32 "
        "{%0,%1,%2,%3}, {%4,%5,%6,%7}, {%8,%9}, {%0,%1,%2,%3};"
        : "+f"(c[0]), "+f"(c[1]), "+f"(c[2]), "+f"(c[3])
        : "r"(a[0]), "r"(a[1]), "r"(a[2]), "r"(a[3]), "r"(b[0]), "r"(b[1]));
}

// ---------------- fp16 tensor-core GEMM ----------------
// C = act(alpha * A @ op(B) + bias).  A [M,K] half row-major.
// TB=1: B [N,K] half; TB=0: B [K,N] half. OUTH=1: C half, else C float.
// CTA tile 128x256, warp 64x64 (2x4 warps), BK=32, 4-stage cp.async pipeline.
template<int TB, int ACT, int OUTH>
__global__ void __launch_bounds__(256, 1)
mma_gemm_k(const __half* __restrict__ A, const __half* __restrict__ B,
           const float* __restrict__ bias, void* __restrict__ Cv,
           int K, int lda, int ldb, int ldc,
           long sAb, long sAh, long sBb, long sBh, long sCb, long sCh,
           int nh, float alpha)
{
    constexpr int BP = TB ? BP1 : BP0;
    constexpr int STG_H = TB ? STG1_H : STG0_H;
    constexpr uint32_t STG_B = STG_H * 2;
    constexpr uint32_t AE_B = AE_H * 2;

    extern __shared__ __half smem[];
    uint32_t sb = (uint32_t)__cvta_generic_to_shared(smem);

    int tid = threadIdx.x;
    int wid = tid >> 5, lane = tid & 31;
    int gq = lane >> 2, gr = lane & 3;
    int wm0 = (wid >> 2) * 64;
    int wn0 = (wid & 3) * 64;

    int z = blockIdx.z, bb = z / nh, hh = z - bb * nh;
    A += bb * sAb + hh * sAh;
    B += bb * sBb + hh * sBh;
    int m0 = blockIdx.y * 128, n0 = blockIdx.x * 256;

    float acc[4][8][4];
    #pragma unroll
    for (int i = 0; i < 4; i++)
        #pragma unroll
        for (int j = 0; j < 8; j++)
            #pragma unroll
            for (int q = 0; q < 4; q++) acc[i][j][q] = 0.f;

    auto ldst = [&](int s, int k0) {
        uint32_t base = sb + s * STG_B;
        // A: 128 rows x 32 halves = 512 16B-chunks
        #pragma unroll
        for (int i = 0; i < 2; i++) {
            int ch = tid + 256 * i;
            int c = ch >> 7, row = ch & 127;
            cpa(base + (uint32_t)(row * AP + c * 8) * 2,
                A + (long)(m0 + row) * lda + k0 + c * 8);
        }
        uint32_t bbase = base + AE_B;
        if (TB) {
            // B: 256 rows x 32 halves = 1024 chunks
            #pragma unroll
            for (int i = 0; i < 4; i++) {
                int ch = tid + 256 * i;
                int c = ch >> 8, row = ch & 255;
                cpa(bbase + (uint32_t)(row * BP + c * 8) * 2,
                    B + (long)(n0 + row) * ldb + k0 + c * 8);
            }
        } else {
            // B: 32 k-rows x 256 halves = 1024 chunks
            #pragma unroll
            for (int i = 0; i < 4; i++) {
                int ch = tid + 256 * i;
                int row = ch >> 5, c = ch & 31;
                cpa(bbase + (uint32_t)(row * BP + c * 8) * 2,
                    B + (long)(k0 + row) * ldb + n0 + c * 8);
            }
        }
        asm volatile("cp.async.commit_group;" ::: "memory");
    };

    int nk = K / 32;
    ldst(0, 0); ldst(1, 32); ldst(2, 64);

    uint32_t a_lo = (uint32_t)((lane & 15) * AP + (lane >> 4) * 8) * 2;
    uint32_t b_lo = (uint32_t)((lane & 15) * BP + (lane >> 4) * 8) * 2;

    for (int it = 0; it < nk; it++) {
        asm volatile("cp.async.wait_group 2;" ::: "memory");
        __syncthreads();
        if (it + 3 < nk) ldst((it + 3) & 3, (it + 3) * 32);
        else asm volatile("cp.async.commit_group;" ::: "memory");

        uint32_t sbase = sb + (uint32_t)(it & 3) * STG_B;
        uint32_t aA = sbase + a_lo;
        uint32_t aB = sbase + AE_B + b_lo;

        #pragma unroll
        for (int kk = 0; kk < 2; kk++) {
            uint32_t afr[4][4];
            #pragma unroll
            for (int mi = 0; mi < 4; mi++)
                LDSM4(afr[mi][0], afr[mi][1], afr[mi][2], afr[mi][3],
                      aA + (uint32_t)((wm0 + mi * 16) * AP) * 2 + kk * 32);
            uint32_t bfr[8][2];
            #pragma unroll
            for (int nj = 0; nj < 4; nj++) {
                uint32_t r0, r1, r2, r3;
                if (TB) {
                    LDSM4(r0, r1, r2, r3,
                          aB + (uint32_t)((wn0 + nj * 16) * BP) * 2 + kk * 32);
                    bfr[2*nj][0] = r0; bfr[2*nj][1] = r2;
                    bfr[2*nj+1][0] = r1; bfr[2*nj+1][1] = r3;
                } else {
                    LDSM4T(r0, r1, r2, r3,
                           aB + (uint32_t)(kk * 16 * BP) * 2 + (uint32_t)(wn0 + nj * 16) * 2);
                    bfr[2*nj][0] = r0; bfr[2*nj][1] = r1;
                    bfr[2*nj+1][0] = r2; bfr[2*nj+1][1] = r3;
                }
            }
            #pragma unroll
            for (int mi = 0; mi < 4; mi++)
                #pragma unroll
                for (int ni = 0; ni < 8; ni++)
                    mma16(acc[mi][ni], afr[mi], bfr[ni]);
        }
    }

    // epilogue
    #pragma unroll
    for (int mi = 0; mi < 4; mi++) {
        int r0 = m0 + wm0 + mi * 16 + gq;
        #pragma unroll
        for (int ni = 0; ni < 8; ni++) {
            int c0 = n0 + wn0 + ni * 8 + gr * 2;
            float bz0 = 0.f, bz1 = 0.f;
            if (bias) { bz0 = bias[c0]; bz1 = bias[c0 + 1]; }
            #pragma unroll
            for (int half_i = 0; half_i < 2; half_i++) {
                float x = acc[mi][ni][half_i * 2 + 0] * alpha + bz0;
                float y = acc[mi][ni][half_i * 2 + 1] * alpha + bz1;
                if (ACT == 1) { x = fmaxf(x, 0.f); y = fmaxf(y, 0.f); }
                if (ACT == 2) { x = (x >= 0.f) ? x : 0.01f * x; y = (y >= 0.f) ? y : 0.01f * y; }
                long off = (long)(r0 + half_i * 8) * ldc + c0 + bb * sCb + hh * sCh;
                if (OUTH) {
                    *reinterpret_cast<__half2*>((__half*)Cv + off) = __floats2half2_rn(x, y);
                } else {
                    float2 v; v.x = x; v.y = y;
                    *reinterpret_cast<float2*>((float*)Cv + off) = v;
                }
            }
        }
    }
}

// ---------------- weight convert fp32 -> fp16 ----------------
__global__ void cvt_k(const float* __restrict__ in, __half* __restrict__ out, long n4)
{
    long i = (long)blockIdx.x * 256 + threadIdx.x;
    if (i >= n4) return;
    float4 v = reinterpret_cast<const float4*>(in)[i];
    __half2* o = reinterpret_cast<__half2*>(out) + i * 2;
    o[0] = __floats2half2_rn(v.x, v.y);
    o[1] = __floats2half2_rn(v.z, v.w);
}

// ---------------- softmax: fp32 in -> fp16 out (1 pass) ----------------
__global__ void softmax_k(const float* __restrict__ att, __half* __restrict__ att16, int causal)
{
    int q = blockIdx.x;
    int z = blockIdx.y;
    const float* p = att + ((long)z * Ss + q) * Ss;
    __half* o = att16 + ((long)z * Ss + q) * Ss;
    int len = causal ? (q + 1) : Ss;
    int tid = threadIdx.x;
    __shared__ float sh[8];

    float v0 = (tid < len) ? p[tid] : -1e30f;
    float v1 = (tid + 256 < len) ? p[tid + 256] : -1e30f;
    float mx = fmaxf(v0, v1);
    #pragma unroll
    for (int o2 = 16; o2; o2 >>= 1) mx = fmaxf(mx, __shfl_xor_sync(~0u, mx, o2));
    if ((tid & 31) == 0) sh[tid >> 5] = mx;
    __syncthreads();
    mx = sh[0];
    #pragma unroll
    for (int w = 1; w < 8; w++) mx = fmaxf(mx, sh[w]);

    float e0 = (tid < len) ? __expf(v0 - mx) : 0.f;
    float e1 = (tid + 256 < len) ? __expf(v1 - mx) : 0.f;
    float s = e0 + e1;
    #pragma unroll
    for (int o2 = 16; o2; o2 >>= 1) s += __shfl_xor_sync(~0u, s, o2);
    __syncthreads();
    if ((tid & 31) == 0) sh[tid >> 5] = s;
    __syncthreads();
    s = 0.f;
    #pragma unroll
    for (int w = 0; w < 8; w++) s += sh[w];
    float inv = 1.f / s;

    o[tid]       = __float2half_rn(e0 * inv);
    o[tid + 256] = __float2half_rn(e1 * inv);
}

// ---------------- h = LN(h + delta); also write h16 ----------------
__global__ void ln_add_k(float* __restrict__ h, __half* __restrict__ h16,
                         const float* __restrict__ d,
                         const float* __restrict__ w, const float* __restrict__ b)
{
    long row = blockIdx.x;
    float* x = h + row * Dd;
    __half* x16 = h16 + row * Dd;
    const float* dd = d + row * Dd;
    int tid = threadIdx.x;
    __shared__ float sh[256];

    float v[4];
    float s = 0.f;
    #pragma unroll
    for (int t = 0; t < 4; t++) { int i = tid + t * 256; v[t] = x[i] + dd[i]; s += v[t]; }
    sh[tid] = s; __syncthreads();
    for (int st = 128; st > 0; st >>= 1) { if (tid < st) sh[tid] += sh[tid + st]; __syncthreads(); }
    float mean = sh[0] * (1.f / Dd); __syncthreads();

    float s2 = 0.f;
    #pragma unroll
    for (int t = 0; t < 4; t++) { float u = v[t] - mean; s2 += u * u; }
    sh[tid] = s2; __syncthreads();
    for (int st = 128; st > 0; st >>= 1) { if (tid < st) sh[tid] += sh[tid + st]; __syncthreads(); }
    float rstd = rsqrtf(sh[0] * (1.f / Dd) + 1e-5f);

    #pragma unroll
    for (int t = 0; t < 4; t++) {
        int i = tid + t * 256;
        float r = (v[t] - mean) * rstd * w[i] + b[i];
        x[i] = r;
        x16[i] = __float2half_rn(r);
    }
}

// ---------------- input projection stage 1 (half out) ----------------
__global__ void build1_k(const float* __restrict__ tgtn, const float* __restrict__ bos,
                         const float* __restrict__ w1, const float* __restrict__ b1,
                         __half* __restrict__ out)
{
    long idx = (long)blockIdx.x * 256 + threadIdx.x;
    long row = idx >> 9;
    int j = (int)(idx & 511);
    int bb = (int)(row >> 9);
    int s = (int)(row & 511);
    float t = (s == 0) ? bos[0] : tgtn[bb * Ls + s - 1];
    float v = t * w1[j] + b1[j];
    out[idx] = __float2half_rn((v >= 0.f) ? v : 0.01f * v);
}

// ---------------- assemble tgt(+PE) -> h,h16 and mem16 ----------------
__global__ void build2_k(const float* __restrict__ x2, const float* __restrict__ gs,
                         const float* __restrict__ prev, const float* __restrict__ cur,
                         float* __restrict__ h, __half* __restrict__ h16,
                         __half* __restrict__ mem16)
{
    int row = blockIdx.x;
    int bb = row >> 9;
    int s = row & 511;
    long ob = (long)row * Dd;
    for (int i = threadIdx.x; i < Dd; i += 256) {
        float tv, mv;
        if (i < HIDh) {
            int jj = i & ~1;
            float div = __expf((float)jj * (-9.210340371976184f / 512.f));
            double ang = (double)s * (double)div;
            double r = ang - 6.283185307179586 * rint(ang * 0.15915494309189535);
            float fr = (float)r;
            float pe = (i & 1) ? cosf(fr) : sinf(fr);
            tv = x2[(long)row * HIDh + i] + pe;
            mv = gs[(long)row * HIDh + i];
        } else if (i < HIDh + EAe) {
            float a = prev[bb * EAe + (i - HIDh)];
            tv = a; mv = a;
        } else {
            float a = cur[bb * EAe + (i - HIDh - EAe)];
            tv = a; mv = a;
        }
        h[ob + i] = tv;
        h16[ob + i] = __float2half_rn(tv);
        mem16[ob + i] = __float2half_rn(mv);
    }
}

// ---------------- final: y2 = y1 @ w2^T + b2, masked ----------------
__global__ void final_k(const float* __restrict__ y1, const float* __restrict__ w2,
                        const float* __restrict__ b2, const int* __restrict__ basis,
                        float* __restrict__ out)
{
    int idx = blockIdx.x * 8 + (threadIdx.x >> 5);
    if (idx >= Bb * Ls) return;
    int bb = idx / Ls, l = idx % Ls;
    const float* r = y1 + ((long)bb * Ss + l + 1) * HIDh;
    int lane = threadIdx.x & 31;
    float s = 0.f;
    for (int j = lane; j < HIDh; j += 32) s += r[j] * w2[j];
    #pragma unroll
    for (int o = 16; o; o >>= 1) s += __shfl_xor_sync(0xffffffffu, s, o);
    if (lane == 0) out[idx] = (l < basis[bb]) ? (s + b2[0]) : 0.f;
}

// ---------------- host-side launcher ----------------
static void hgemm(int TB, int ACT, int OUTH,
                  const __half* A, const __half* B, const float* bias, void* C,
                  int M, int N, int K, int lda, int ldb, int ldc,
                  long sAb, long sAh, long sBb, long sBh, long sCb, long sCh,
                  int nb, int nh, float alpha)
{
    dim3 grid(N / 256, M / 128, nb * nh);
#define HCALL(tb, act, oh, sm) mma_gemm_k<tb, act, oh><<<grid, 256, sm>>>( \
        A, B, bias, C, K, lda, ldb, ldc, sAb, sAh, sBb, sBh, sCb, sCh, nh, alpha)
    if (TB == 1 && ACT == 0 && OUTH == 1) HCALL(1, 0, 1, SMEM_TB1);
    else if (TB == 1 && ACT == 0 && OUTH == 0) HCALL(1, 0, 0, SMEM_TB1);
    else if (TB == 1 && ACT == 1 && OUTH == 1) HCALL(1, 1, 1, SMEM_TB1);
    else if (TB == 1 && ACT == 2 && OUTH == 0) HCALL(1, 2, 0, SMEM_TB1);
    else HCALL(0, 0, 1, SMEM_TB0);
#undef HCALL
}

static void cvt(const float* in, __half* out, long n)
{
    long n4 = n / 4;
    cvt_k<<<(unsigned)((n4 + 255) / 256), 256>>>(in, out, n4);
}

extern "C" void kernel_launch(void* const* d_in, const int* in_sizes, int n_in,
                              void* d_out, int out_size)
{
    const float* gs      = (const float*)d_in[0];
    const float* prev    = (const float*)d_in[1];
    const float* cur     = (const float*)d_in[2];
    const float* tgtn    = (const float*)d_in[3];
    const float* bos     = (const float*)d_in[4];
    const float* inp_w1  = (const float*)d_in[5];
    const float* inp_b1  = (const float*)d_in[6];
    const float* inp_w2  = (const float*)d_in[7];
    const float* inp_b2  = (const float*)d_in[8];
    const float* sa_qkv_w= (const float*)d_in[9];
    const float* sa_qkv_b= (const float*)d_in[10];
    const float* sa_out_w= (const float*)d_in[11];
    const float* sa_out_b= (const float*)d_in[12];
    const float* ca_qkv_w= (const float*)d_in[13];
    const float* ca_qkv_b= (const float*)d_in[14];
    const float* ca_out_w= (const float*)d_in[15];
    const float* ca_out_b= (const float*)d_in[16];
    const float* ln_w    = (const float*)d_in[17];
    const float* ln_b    = (const float*)d_in[18];
    const float* ff_w1   = (const float*)d_in[19];
    const float* ff_b1   = (const float*)d_in[20];
    const float* ff_w2   = (const float*)d_in[21];
    const float* ff_b2   = (const float*)d_in[22];
    const float* proj_w1 = (const float*)d_in[23];
    const float* proj_b1 = (const float*)d_in[24];
    const float* proj_w2 = (const float*)d_in[25];
    const float* proj_b2 = (const float*)d_in[26];
    const int*   basis   = (const int*)d_in[27];

    cudaFuncSetAttribute(mma_gemm_k<1,0,1>, cudaFuncAttributeMaxDynamicSharedMemorySize, SMEM_TB1);
    cudaFuncSetAttribute(mma_gemm_k<1,0,0>, cudaFuncAttributeMaxDynamicSharedMemorySize, SMEM_TB1);
    cudaFuncSetAttribute(mma_gemm_k<1,1,1>, cudaFuncAttributeMaxDynamicSharedMemorySize, SMEM_TB1);
    cudaFuncSetAttribute(mma_gemm_k<1,2,0>, cudaFuncAttributeMaxDynamicSharedMemorySize, SMEM_TB1);
    cudaFuncSetAttribute(mma_gemm_k<0,0,1>, cudaFuncAttributeMaxDynamicSharedMemorySize, SMEM_TB0);

    float *h, *x2, *att;
    __half *h16, *mem16, *qkv16, *att16, *xh, *wh;
    cudaGetSymbolAddress((void**)&h,    d_h);
    cudaGetSymbolAddress((void**)&x2,   d_x2);
    cudaGetSymbolAddress((void**)&att,  d_att);
    cudaGetSymbolAddress((void**)&h16,  d_h16);
    cudaGetSymbolAddress((void**)&mem16,d_mem16);
    cudaGetSymbolAddress((void**)&qkv16,d_qkv16);
    cudaGetSymbolAddress((void**)&att16,d_att16);
    cudaGetSymbolAddress((void**)&xh,   d_xh);
    cudaGetSymbolAddress((void**)&wh,   d_wh);

    // ---- convert all weights to fp16 ----
    cvt(sa_qkv_w, wh + W_SAQKV, 3L*3072*1024);
    cvt(sa_out_w, wh + W_SAOUT, 3L*1024*1024);
    cvt(ca_qkv_w, wh + W_CAQKV, 3L*3072*1024);
    cvt(ca_out_w, wh + W_CAOUT, 3L*1024*1024);
    cvt(ff_w1,    wh + W_FFW1,  3L*2048*1024);
    cvt(ff_w2,    wh + W_FFW2,  3L*1024*2048);
    cvt(inp_w2,   wh + W_INPW2, 512L*512);
    cvt(proj_w1,  wh + W_PROJW1,512L*1024);

    const int M = Bb * Ss;          // 8192
    const long zero = 0;

    // ---- build tgt & mem ----
    build1_k<<<(M * HIDh) / 256, 256>>>(tgtn, bos, inp_w1, inp_b1, xh);
    hgemm(1, 0, 0, xh, wh + W_INPW2, inp_b2, x2, M, HIDh, HIDh, HIDh, HIDh, HIDh,
          zero, zero, zero, zero, zero, zero, 1, 1, 1.f);
    build2_k<<<M, 256>>>(x2, gs, prev, cur, h, h16, mem16);

    const long sTok  = (long)Ss * 3072;
    const long sAttB = (long)NHh * Ss * Ss;
    const long sAttH = (long)Ss * Ss;
    const float iscale = 1.f / 16.f;         // 1/sqrt(hd)

    for (int l = 0; l < 3; l++) {
        // ===== self-attention =====
        hgemm(1, 0, 1, h16, wh + W_SAQKV + (long)l * 3 * Dd * Dd, sa_qkv_b + (long)l * 3 * Dd,
              qkv16, M, 3 * Dd, Dd, Dd, Dd, 3 * Dd, zero, zero, zero, zero, zero, zero, 1, 1, 1.f);
        hgemm(1, 0, 0, qkv16, qkv16 + Dd, nullptr, att, Ss, Ss, HDh, 3 * Dd, 3 * Dd, Ss,
              sTok, (long)HDh, sTok, (long)HDh, sAttB, sAttH, Bb, NHh, iscale);
        softmax_k<<<dim3(Ss, Bb * NHh), 256>>>(att, att16, 1);
        hgemm(0, 0, 1, att16, qkv16 + 2 * Dd, nullptr, xh, Ss, HDh, Ss, Ss, 3 * Dd, Dd,
              sAttB, sAttH, sTok, (long)HDh, (long)Ss * Dd, (long)HDh, Bb, NHh, 1.f);
        hgemm(1, 0, 0, xh, wh + W_SAOUT + (long)l * Dd * Dd, sa_out_b + (long)l * Dd, x2,
              M, Dd, Dd, Dd, Dd, Dd, zero, zero, zero, zero, zero, zero, 1, 1, 1.f);
        ln_add_k<<<M, 256>>>(h, h16, x2, ln_w + (long)(l * 3 + 0) * Dd, ln_b + (long)(l * 3 + 0) * Dd);

        // ===== cross-attention =====
        hgemm(1, 0, 1, h16, wh + W_CAQKV + (long)l * 3 * Dd * Dd, ca_qkv_b + (long)l * 3 * Dd,
              qkv16, M, Dd, Dd, Dd, Dd, 3 * Dd, zero, zero, zero, zero, zero, zero, 1, 1, 1.f);
        hgemm(1, 0, 1, mem16, wh + W_CAQKV + (long)l * 3 * Dd * Dd + (long)Dd * Dd,
              ca_qkv_b + (long)l * 3 * Dd + Dd, qkv16 + Dd,
              M, 2 * Dd, Dd, Dd, Dd, 3 * Dd, zero, zero, zero, zero, zero, zero, 1, 1, 1.f);
        hgemm(1, 0, 0, qkv16, qkv16 + Dd, nullptr, att, Ss, Ss, HDh, 3 * Dd, 3 * Dd, Ss,
              sTok, (long)HDh, sTok, (long)HDh, sAttB, sAttH, Bb, NHh, iscale);
        softmax_k<<<dim3(Ss, Bb * NHh), 256>>>(att, att16, 0);
        hgemm(0, 0, 1, att16, qkv16 + 2 * Dd, nullptr, xh, Ss, HDh, Ss, Ss, 3 * Dd, Dd,
              sAttB, sAttH, sTok, (long)HDh, (long)Ss * Dd, (long)HDh, Bb, NHh, 1.f);
        hgemm(1, 0, 0, xh, wh + W_CAOUT + (long)l * Dd * Dd, ca_out_b + (long)l * Dd, x2,
              M, Dd, Dd, Dd, Dd, Dd, zero, zero, zero, zero, zero, zero, 1, 1, 1.f);
        ln_add_k<<<M, 256>>>(h, h16, x2, ln_w + (long)(l * 3 + 1) * Dd, ln_b + (long)(l * 3 + 1) * Dd);

        // ===== feed-forward =====
        hgemm(1, 1, 1, h16, wh + W_FFW1 + (long)l * DFFf * Dd, ff_b1 + (long)l * DFFf, xh,
              M, DFFf, Dd, Dd, Dd, DFFf, zero, zero, zero, zero, zero, zero, 1, 1, 1.f);
        hgemm(1, 0, 0, xh, wh + W_FFW2 + (long)l * Dd * DFFf, ff_b2 + (long)l * Dd, x2,
              M, Dd, DFFf, DFFf, DFFf, Dd, zero, zero, zero, zero, zero, zero, 1, 1, 1.f);
        ln_add_k<<<M, 256>>>(h, h16, x2, ln_w + (long)(l * 3 + 2) * Dd, ln_b + (long)(l * 3 + 2) * Dd);
    }

    // ---- output head ----
    hgemm(1, 2, 0, h16, wh + W_PROJW1, proj_b1, x2, M, HIDh, Dd, Dd, Dd, HIDh,
          zero, zero, zero, zero, zero, zero, 1, 1, 1.f);
    final_k<<<(Bb * Ls + 7) / 8, 256>>>(x2, proj_w2, proj_b2, basis, (float*)d_out);
}

// round 9
// speedup vs baseline: 4.1089x; 1.0095x over previous
#include <cuda_runtime.h>
#include <cuda_fp16.h>
#include <math.h>
#include <stdint.h>

// ---------------- problem constants ----------------
#define Bb 16
#define Ls 511
#define Ss 512
#define Dd 1024
#define HIDh 512
#define DFFf 2048
#define EAe 256
#define NHh 4
#define HDh 256   // D/NH

// ---------------- GEMM tile config: CTA 128x128, warp 64x32, BK=32, 4 stages ----
#define AP 40                     // A smem pitch (halves)
#define BP1 40                    // B smem pitch, TB=1
#define BP0 136                   // B smem pitch, TB=0 (128 + 8 pad)
#define AE_H (128*AP)             // 5120 halves per A stage
#define STG1_H (AE_H + 128*BP1)   // 10240
#define STG0_H (AE_H + 32*BP0)    // 9472
#define SMEM_TB1 (STG1_H*2*4)     // 81920 B
#define SMEM_TB0 (STG0_H*2*4)     // 75776 B

// ---------------- scratch (static device memory) ----------------
__device__ float  d_h   [8192L*1024];
__device__ float  d_x2  [8192L*1024];
__device__ __half d_h16 [8192L*1024];
__device__ __half d_mem16[8192L*1024];
__device__ __half d_qkv16[8192L*3072];
__device__ __half d_att16[64L*512*512];
__device__ __half d_xh  [8192L*2048];
__device__ __half d_wh  [38535168];

// weight-region offsets in d_wh (halves)
#define W_SAQKV  0L
#define W_SAOUT  9437184L
#define W_CAQKV  12582912L
#define W_CAOUT  22020096L
#define W_FFW1   25165824L
#define W_FFW2   31457280L
#define W_INPW2  37748736L
#define W_PROJW1 38010880L

// ---------------- asm helpers ----------------
__device__ __forceinline__ void cpa(uint32_t d, const __half* s) {
    asm volatile("cp.async.cg.shared.global [%0], [%1], 16;" :: "r"(d), "l"(s));
}
#define LDSM4(r0,r1,r2,r3,a) \
    asm volatile("ldmatrix.sync.aligned.m8n8.x4.shared.b16 {%0,%1,%2,%3}, [%4];" \
                 : "=r"(r0),"=r"(r1),"=r"(r2),"=r"(r3) : "r"(a))
#define LDSM4T(r0,r1,r2,r3,a) \
    asm volatile("ldmatrix.sync.aligned.m8n8.x4.trans.shared.b16 {%0,%1,%2,%3}, [%4];" \
                 : "=r"(r0),"=r"(r1),"=r"(r2),"=r"(r3) : "r"(a))

__device__ __forceinline__ void mma16(float* c, const uint32_t* a, const uint32_t* b) {
    asm volatile(
        "mma.sync.aligned.m16n8k16.row.col.f32.f16.f16.f32 "
        "{%0,%1,%2,%3}, {%4,%5,%6,%7}, {%8,%9}, {%0,%1,%2,%3};"
        : "+f"(c[0]), "+f"(c[1]), "+f"(c[2]), "+f"(c[3])
        : "r"(a[0]), "r"(a[1]), "r"(a[2]), "r"(a[3]), "r"(b[0]), "r"(b[1]));
}

// ---------------- fp16 tensor-core GEMM ----------------
// C = act(alpha * A @ op(B) + bias).  A [M,K] half row-major.
// TB=1: B [N,K]; TB=0: B [K,N]. OUTH=1: C half, else C float.
// CTA 128x128, 8 warps (2x4), warp tile 64x32, 4-stage cp.async, 2 CTAs/SM.
template<int TB, int ACT, int OUTH>
__global__ void __launch_bounds__(256, 2)
mma_gemm_k(const __half* __restrict__ A, const __half* __restrict__ B,
           const float* __restrict__ bias, void* __restrict__ Cv,
           int K, int lda, int ldb, int ldc,
           long sAb, long sAh, long sBb, long sBh, long sCb, long sCh,
           int nh, float alpha)
{
    constexpr int BP = TB ? BP1 : BP0;
    constexpr int STG_H = TB ? STG1_H : STG0_H;
    constexpr uint32_t STG_B = STG_H * 2;
    constexpr uint32_t AE_B = AE_H * 2;

    extern __shared__ __half smem[];
    uint32_t sb = (uint32_t)__cvta_generic_to_shared(smem);

    int tid = threadIdx.x;
    int wid = tid >> 5, lane = tid & 31;
    int gq = lane >> 2, gr = lane & 3;
    int wm0 = (wid >> 2) * 64;     // 2 warp rows
    int wn0 = (wid & 3) * 32;      // 4 warp cols

    int z = blockIdx.z, bb = z / nh, hh = z - bb * nh;
    A += bb * sAb + hh * sAh;
    B += bb * sBb + hh * sBh;
    int m0 = blockIdx.y * 128, n0 = blockIdx.x * 128;

    float acc[4][4][4];
    #pragma unroll
    for (int i = 0; i < 4; i++)
        #pragma unroll
        for (int j = 0; j < 4; j++)
            #pragma unroll
            for (int q = 0; q < 4; q++) acc[i][j][q] = 0.f;

    auto ldst = [&](int s, int k0) {
        uint32_t base = sb + s * STG_B;
        // A: 128 rows x 32 halves = 512 16B-chunks
        #pragma unroll
        for (int i = 0; i < 2; i++) {
            int ch = tid + 256 * i;
            int c = ch >> 7, row = ch & 127;
            cpa(base + (uint32_t)(row * AP + c * 8) * 2,
                A + (long)(m0 + row) * lda + k0 + c * 8);
        }
        uint32_t bbase = base + AE_B;
        if (TB) {
            // B: 128 rows x 32 halves = 512 chunks
            #pragma unroll
            for (int i = 0; i < 2; i++) {
                int ch = tid + 256 * i;
                int c = ch >> 7, row = ch & 127;
                cpa(bbase + (uint32_t)(row * BP + c * 8) * 2,
                    B + (long)(n0 + row) * ldb + k0 + c * 8);
            }
        } else {
            // B: 32 k-rows x 128 halves = 512 chunks
            #pragma unroll
            for (int i = 0; i < 2; i++) {
                int ch = tid + 256 * i;
                int row = ch >> 4, c = ch & 15;
                cpa(bbase + (uint32_t)(row * BP + c * 8) * 2,
                    B + (long)(k0 + row) * ldb + n0 + c * 8);
            }
        }
        asm volatile("cp.async.commit_group;" ::: "memory");
    };

    int nk = K / 32;
    ldst(0, 0); ldst(1, 32); ldst(2, 64);

    uint32_t a_lo = (uint32_t)((lane & 15) * AP + (lane >> 4) * 8) * 2;
    uint32_t b_lo = (uint32_t)((lane & 15) * BP + (lane >> 4) * 8) * 2;

    for (int it = 0; it < nk; it++) {
        asm volatile("cp.async.wait_group 2;" ::: "memory");
        __syncthreads();
        if (it + 3 < nk) ldst((it + 3) & 3, (it + 3) * 32);
        else asm volatile("cp.async.commit_group;" ::: "memory");

        uint32_t sbase = sb + (uint32_t)(it & 3) * STG_B;
        uint32_t aA = sbase + a_lo;
        uint32_t aB = sbase + AE_B + b_lo;

        #pragma unroll
        for (int kk = 0; kk < 2; kk++) {
            uint32_t afr[4][4];
            #pragma unroll
            for (int mi = 0; mi < 4; mi++)
                LDSM4(afr[mi][0], afr[mi][1], afr[mi][2], afr[mi][3],
                      aA + (uint32_t)((wm0 + mi * 16) * AP) * 2 + kk * 32);
            uint32_t bfr[4][2];
            #pragma unroll
            for (int nj = 0; nj < 2; nj++) {
                uint32_t r0, r1, r2, r3;
                if (TB) {
                    LDSM4(r0, r1, r2, r3,
                          aB + (uint32_t)((wn0 + nj * 16) * BP) * 2 + kk * 32);
                    bfr[2*nj][0] = r0; bfr[2*nj][1] = r2;
                    bfr[2*nj+1][0] = r1; bfr[2*nj+1][1] = r3;
                } else {
                    LDSM4T(r0, r1, r2, r3,
                           aB + (uint32_t)(kk * 16 * BP) * 2 + (uint32_t)(wn0 + nj * 16) * 2);
                    bfr[2*nj][0] = r0; bfr[2*nj][1] = r1;
                    bfr[2*nj+1][0] = r2; bfr[2*nj+1][1] = r3;
                }
            }
            #pragma unroll
            for (int mi = 0; mi < 4; mi++)
                #pragma unroll
                for (int ni = 0; ni < 4; ni++)
                    mma16(acc[mi][ni], afr[mi], bfr[ni]);
        }
    }

    // epilogue
    #pragma unroll
    for (int mi = 0; mi < 4; mi++) {
        int r0 = m0 + wm0 + mi * 16 + gq;
        #pragma unroll
        for (int ni = 0; ni < 4; ni++) {
            int c0 = n0 + wn0 + ni * 8 + gr * 2;
            float bz0 = 0.f, bz1 = 0.f;
            if (bias) { bz0 = bias[c0]; bz1 = bias[c0 + 1]; }
            #pragma unroll
            for (int hi = 0; hi < 2; hi++) {
                float x = acc[mi][ni][hi * 2 + 0] * alpha + bz0;
                float y = acc[mi][ni][hi * 2 + 1] * alpha + bz1;
                if (ACT == 1) { x = fmaxf(x, 0.f); y = fmaxf(y, 0.f); }
                if (ACT == 2) { x = (x >= 0.f) ? x : 0.01f * x; y = (y >= 0.f) ? y : 0.01f * y; }
                long off = (long)(r0 + hi * 8) * ldc + c0 + bb * sCb + hh * sCh;
                if (OUTH) {
                    *reinterpret_cast<__half2*>((__half*)Cv + off) = __floats2half2_rn(x, y);
                } else {
                    float2 v; v.x = x; v.y = y;
                    *reinterpret_cast<float2*>((float*)Cv + off) = v;
                }
            }
        }
    }
}

// ---------------- weight convert fp32 -> fp16 ----------------
__global__ void cvt_k(const float* __restrict__ in, __half* __restrict__ out, long n4)
{
    long i = (long)blockIdx.x * 256 + threadIdx.x;
    if (i >= n4) return;
    float4 v = reinterpret_cast<const float4*>(in)[i];
    __half2* o = reinterpret_cast<__half2*>(out) + i * 2;
    o[0] = __floats2half2_rn(v.x, v.y);
    o[1] = __floats2half2_rn(v.z, v.w);
}

// ---------------- softmax: fp16 in-place (scores -> probabilities) ----------------
__global__ void softmax_k(__half* __restrict__ att, int causal)
{
    int q = blockIdx.x;
    int z = blockIdx.y;
    __half* p = att + ((long)z * Ss + q) * Ss;
    int len = causal ? (q + 1) : Ss;
    int tid = threadIdx.x;
    __shared__ float sh[8];

    float v0 = (tid < len) ? __half2float(p[tid]) : -1e30f;
    float v1 = (tid + 256 < len) ? __half2float(p[tid + 256]) : -1e30f;
    float mx = fmaxf(v0, v1);
    #pragma unroll
    for (int o2 = 16; o2; o2 >>= 1) mx = fmaxf(mx, __shfl_xor_sync(~0u, mx, o2));
    if ((tid & 31) == 0) sh[tid >> 5] = mx;
    __syncthreads();
    mx = sh[0];
    #pragma unroll
    for (int w = 1; w < 8; w++) mx = fmaxf(mx, sh[w]);

    float e0 = (tid < len) ? __expf(v0 - mx) : 0.f;
    float e1 = (tid + 256 < len) ? __expf(v1 - mx) : 0.f;
    float s = e0 + e1;
    #pragma unroll
    for (int o2 = 16; o2; o2 >>= 1) s += __shfl_xor_sync(~0u, s, o2);
    __syncthreads();
    if ((tid & 31) == 0) sh[tid >> 5] = s;
    __syncthreads();
    s = 0.f;
    #pragma unroll
    for (int w = 0; w < 8; w++) s += sh[w];
    float inv = 1.f / s;

    p[tid]       = __float2half_rn(e0 * inv);
    p[tid + 256] = __float2half_rn(e1 * inv);
}

// ---------------- h = LN(h + delta); also write h16 ----------------
__global__ void ln_add_k(float* __restrict__ h, __half* __restrict__ h16,
                         const float* __restrict__ d,
                         const float* __restrict__ w, const float* __restrict__ b)
{
    long row = blockIdx.x;
    float* x = h + row * Dd;
    __half* x16 = h16 + row * Dd;
    const float* dd = d + row * Dd;
    int tid = threadIdx.x;
    __shared__ float sh[256];

    float v[4];
    float s = 0.f;
    #pragma unroll
    for (int t = 0; t < 4; t++) { int i = tid + t * 256; v[t] = x[i] + dd[i]; s += v[t]; }
    sh[tid] = s; __syncthreads();
    for (int st = 128; st > 0; st >>= 1) { if (tid < st) sh[tid] += sh[tid + st]; __syncthreads(); }
    float mean = sh[0] * (1.f / Dd); __syncthreads();

    float s2 = 0.f;
    #pragma unroll
    for (int t = 0; t < 4; t++) { float u = v[t] - mean; s2 += u * u; }
    sh[tid] = s2; __syncthreads();
    for (int st = 128; st > 0; st >>= 1) { if (tid < st) sh[tid] += sh[tid + st]; __syncthreads(); }
    float rstd = rsqrtf(sh[0] * (1.f / Dd) + 1e-5f);

    #pragma unroll
    for (int t = 0; t < 4; t++) {
        int i = tid + t * 256;
        float r = (v[t] - mean) * rstd * w[i] + b[i];
        x[i] = r;
        x16[i] = __float2half_rn(r);
    }
}

// ---------------- input projection stage 1 (half out) ----------------
__global__ void build1_k(const float* __restrict__ tgtn, const float* __restrict__ bos,
                         const float* __restrict__ w1, const float* __restrict__ b1,
                         __half* __restrict__ out)
{
    long idx = (long)blockIdx.x * 256 + threadIdx.x;
    long row = idx >> 9;
    int j = (int)(idx & 511);
    int bb = (int)(row >> 9);
    int s = (int)(row & 511);
    float t = (s == 0) ? bos[0] : tgtn[bb * Ls + s - 1];
    float v = t * w1[j] + b1[j];
    out[idx] = __float2half_rn((v >= 0.f) ? v : 0.01f * v);
}

// ---------------- assemble tgt(+PE) -> h,h16 and mem16 ----------------
__global__ void build2_k(const float* __restrict__ x2, const float* __restrict__ gs,
                         const float* __restrict__ prev, const float* __restrict__ cur,
                         float* __restrict__ h, __half* __restrict__ h16,
                         __half* __restrict__ mem16)
{
    int row = blockIdx.x;
    int bb = row >> 9;
    int s = row & 511;
    long ob = (long)row * Dd;
    for (int i = threadIdx.x; i < Dd; i += 256) {
        float tv, mv;
        if (i < HIDh) {
            int jj = i & ~1;
            float div = __expf((float)jj * (-9.210340371976184f / 512.f));
            double ang = (double)s * (double)div;
            double r = ang - 6.283185307179586 * rint(ang * 0.15915494309189535);
            float fr = (float)r;
            float pe = (i & 1) ? cosf(fr) : sinf(fr);
            tv = x2[(long)row * HIDh + i] + pe;
            mv = gs[(long)row * HIDh + i];
        } else if (i < HIDh + EAe) {
            float a = prev[bb * EAe + (i - HIDh)];
            tv = a; mv = a;
        } else {
            float a = cur[bb * EAe + (i - HIDh - EAe)];
            tv = a; mv = a;
        }
        h[ob + i] = tv;
        h16[ob + i] = __float2half_rn(tv);
        mem16[ob + i] = __float2half_rn(mv);
    }
}

// ---------------- final: y2 = y1 @ w2^T + b2, masked ----------------
__global__ void final_k(const float* __restrict__ y1, const float* __restrict__ w2,
                        const float* __restrict__ b2, const int* __restrict__ basis,
                        float* __restrict__ out)
{
    int idx = blockIdx.x * 8 + (threadIdx.x >> 5);
    if (idx >= Bb * Ls) return;
    int bb = idx / Ls, l = idx % Ls;
    const float* r = y1 + ((long)bb * Ss + l + 1) * HIDh;
    int lane = threadIdx.x & 31;
    float s = 0.f;
    for (int j = lane; j < HIDh; j += 32) s += r[j] * w2[j];
    #pragma unroll
    for (int o = 16; o; o >>= 1) s += __shfl_xor_sync(0xffffffffu, s, o);
    if (lane == 0) out[idx] = (l < basis[bb]) ? (s + b2[0]) : 0.f;
}

// ---------------- host-side launcher ----------------
static void hgemm(int TB, int ACT, int OUTH,
                  const __half* A, const __half* B, const float* bias, void* C,
                  int M, int N, int K, int lda, int ldb, int ldc,
                  long sAb, long sAh, long sBb, long sBh, long sCb, long sCh,
                  int nb, int nh, float alpha)
{
    dim3 grid(N / 128, M / 128, nb * nh);
#define HCALL(tb, act, oh, sm) mma_gemm_k<tb, act, oh><<<grid, 256, sm>>>( \
        A, B, bias, C, K, lda, ldb, ldc, sAb, sAh, sBb, sBh, sCb, sCh, nh, alpha)
    if (TB == 1 && ACT == 0 && OUTH == 1) HCALL(1, 0, 1, SMEM_TB1);
    else if (TB == 1 && ACT == 0 && OUTH == 0) HCALL(1, 0, 0, SMEM_TB1);
    else if (TB == 1 && ACT == 1 && OUTH == 1) HCALL(1, 1, 1, SMEM_TB1);
    else if (TB == 1 && ACT == 2 && OUTH == 0) HCALL(1, 2, 0, SMEM_TB1);
    else HCALL(0, 0, 1, SMEM_TB0);
#undef HCALL
}

static void cvt(const float* in, __half* out, long n)
{
    long n4 = n / 4;
    cvt_k<<<(unsigned)((n4 + 255) / 256), 256>>>(in, out, n4);
}

extern "C" void kernel_launch(void* const* d_in, const int* in_sizes, int n_in,
                              void* d_out, int out_size)
{
    const float* gs      = (const float*)d_in[0];
    const float* prev    = (const float*)d_in[1];
    const float* cur     = (const float*)d_in[2];
    const float* tgtn    = (const float*)d_in[3];
    const float* bos     = (const float*)d_in[4];
    const float* inp_w1  = (const float*)d_in[5];
    const float* inp_b1  = (const float*)d_in[6];
    const float* inp_w2  = (const float*)d_in[7];
    const float* inp_b2  = (const float*)d_in[8];
    const float* sa_qkv_w= (const float*)d_in[9];
    const float* sa_qkv_b= (const float*)d_in[10];
    const float* sa_out_w= (const float*)d_in[11];
    const float* sa_out_b= (const float*)d_in[12];
    const float* ca_qkv_w= (const float*)d_in[13];
    const float* ca_qkv_b= (const float*)d_in[14];
    const float* ca_out_w= (const float*)d_in[15];
    const float* ca_out_b= (const float*)d_in[16];
    const float* ln_w    = (const float*)d_in[17];
    const float* ln_b    = (const float*)d_in[18];
    const float* ff_w1   = (const float*)d_in[19];
    const float* ff_b1   = (const float*)d_in[20];
    const float* ff_w2   = (const float*)d_in[21];
    const float* ff_b2   = (const float*)d_in[22];
    const float* proj_w1 = (const float*)d_in[23];
    const float* proj_b1 = (const float*)d_in[24];
    const float* proj_w2 = (const float*)d_in[25];
    const float* proj_b2 = (const float*)d_in[26];
    const int*   basis   = (const int*)d_in[27];

    cudaFuncSetAttribute(mma_gemm_k<1,0,1>, cudaFuncAttributeMaxDynamicSharedMemorySize, SMEM_TB1);
    cudaFuncSetAttribute(mma_gemm_k<1,0,0>, cudaFuncAttributeMaxDynamicSharedMemorySize, SMEM_TB1);
    cudaFuncSetAttribute(mma_gemm_k<1,1,1>, cudaFuncAttributeMaxDynamicSharedMemorySize, SMEM_TB1);
    cudaFuncSetAttribute(mma_gemm_k<1,2,0>, cudaFuncAttributeMaxDynamicSharedMemorySize, SMEM_TB1);
    cudaFuncSetAttribute(mma_gemm_k<0,0,1>, cudaFuncAttributeMaxDynamicSharedMemorySize, SMEM_TB0);

    float *h, *x2;
    __half *h16, *mem16, *qkv16, *att16, *xh, *wh;
    cudaGetSymbolAddress((void**)&h,    d_h);
    cudaGetSymbolAddress((void**)&x2,   d_x2);
    cudaGetSymbolAddress((void**)&h16,  d_h16);
    cudaGetSymbolAddress((void**)&mem16,d_mem16);
    cudaGetSymbolAddress((void**)&qkv16,d_qkv16);
    cudaGetSymbolAddress((void**)&att16,d_att16);
    cudaGetSymbolAddress((void**)&xh,   d_xh);
    cudaGetSymbolAddress((void**)&wh,   d_wh);

    // ---- convert all weights to fp16 ----
    cvt(sa_qkv_w, wh + W_SAQKV, 3L*3072*1024);
    cvt(sa_out_w, wh + W_SAOUT, 3L*1024*1024);
    cvt(ca_qkv_w, wh + W_CAQKV, 3L*3072*1024);
    cvt(ca_out_w, wh + W_CAOUT, 3L*1024*1024);
    cvt(ff_w1,    wh + W_FFW1,  3L*2048*1024);
    cvt(ff_w2,    wh + W_FFW2,  3L*1024*2048);
    cvt(inp_w2,   wh + W_INPW2, 512L*512);
    cvt(proj_w1,  wh + W_PROJW1,512L*1024);

    const int M = Bb * Ss;          // 8192
    const long zero = 0;

    // ---- build tgt & mem ----
    build1_k<<<(M * HIDh) / 256, 256>>>(tgtn, bos, inp_w1, inp_b1, xh);
    hgemm(1, 0, 0, xh, wh + W_INPW2, inp_b2, x2, M, HIDh, HIDh, HIDh, HIDh, HIDh,
          zero, zero, zero, zero, zero, zero, 1, 1, 1.f);
    build2_k<<<M, 256>>>(x2, gs, prev, cur, h, h16, mem16);

    const long sTok  = (long)Ss * 3072;
    const long sAttB = (long)NHh * Ss * Ss;
    const long sAttH = (long)Ss * Ss;
    const float iscale = 1.f / 16.f;         // 1/sqrt(hd)

    for (int l = 0; l < 3; l++) {
        // ===== self-attention =====
        hgemm(1, 0, 1, h16, wh + W_SAQKV + (long)l * 3 * Dd * Dd, sa_qkv_b + (long)l * 3 * Dd,
              qkv16, M, 3 * Dd, Dd, Dd, Dd, 3 * Dd, zero, zero, zero, zero, zero, zero, 1, 1, 1.f);
        hgemm(1, 0, 1, qkv16, qkv16 + Dd, nullptr, att16, Ss, Ss, HDh, 3 * Dd, 3 * Dd, Ss,
              sTok, (long)HDh, sTok, (long)HDh, sAttB, sAttH, Bb, NHh, iscale);
        softmax_k<<<dim3(Ss, Bb * NHh), 256>>>(att16, 1);
        hgemm(0, 0, 1, att16, qkv16 + 2 * Dd, nullptr, xh, Ss, HDh, Ss, Ss, 3 * Dd, Dd,
              sAttB, sAttH, sTok, (long)HDh, (long)Ss * Dd, (long)HDh, Bb, NHh, 1.f);
        hgemm(1, 0, 0, xh, wh + W_SAOUT + (long)l * Dd * Dd, sa_out_b + (long)l * Dd, x2,
              M, Dd, Dd, Dd, Dd, Dd, zero, zero, zero, zero, zero, zero, 1, 1, 1.f);
        ln_add_k<<<M, 256>>>(h, h16, x2, ln_w + (long)(l * 3 + 0) * Dd, ln_b + (long)(l * 3 + 0) * Dd);

        // ===== cross-attention =====
        hgemm(1, 0, 1, h16, wh + W_CAQKV + (long)l * 3 * Dd * Dd, ca_qkv_b + (long)l * 3 * Dd,
              qkv16, M, Dd, Dd, Dd, Dd, 3 * Dd, zero, zero, zero, zero, zero, zero, 1, 1, 1.f);
        hgemm(1, 0, 1, mem16, wh + W_CAQKV + (long)l * 3 * Dd * Dd + (long)Dd * Dd,
              ca_qkv_b + (long)l * 3 * Dd + Dd, qkv16 + Dd,
              M, 2 * Dd, Dd, Dd, Dd, 3 * Dd, zero, zero, zero, zero, zero, zero, 1, 1, 1.f);
        hgemm(1, 0, 1, qkv16, qkv16 + Dd, nullptr, att16, Ss, Ss, HDh, 3 * Dd, 3 * Dd, Ss,
              sTok, (long)HDh, sTok, (long)HDh, sAttB, sAttH, Bb, NHh, iscale);
        softmax_k<<<dim3(Ss, Bb * NHh), 256>>>(att16, 0);
        hgemm(0, 0, 1, att16, qkv16 + 2 * Dd, nullptr, xh, Ss, HDh, Ss, Ss, 3 * Dd, Dd,
              sAttB, sAttH, sTok, (long)HDh, (long)Ss * Dd, (long)HDh, Bb, NHh, 1.f);
        hgemm(1, 0, 0, xh, wh + W_CAOUT + (long)l * Dd * Dd, ca_out_b + (long)l * Dd, x2,
              M, Dd, Dd, Dd, Dd, Dd, zero, zero, zero, zero, zero, zero, 1, 1, 1.f);
        ln_add_k<<<M, 256>>>(h, h16, x2, ln_w + (long)(l * 3 + 1) * Dd, ln_b + (long)(l * 3 + 1) * Dd);

        // ===== feed-forward =====
        hgemm(1, 1, 1, h16, wh + W_FFW1 + (long)l * DFFf * Dd, ff_b1 + (long)l * DFFf, xh,
              M, DFFf, Dd, Dd, Dd, DFFf, zero, zero, zero, zero, zero, zero, 1, 1, 1.f);
        hgemm(1, 0, 0, xh, wh + W_FFW2 + (long)l * Dd * DFFf, ff_b2 + (long)l * Dd, x2,
              M, Dd, DFFf, DFFf, DFFf, Dd, zero, zero, zero, zero, zero, zero, 1, 1, 1.f);
        ln_add_k<<<M, 256>>>(h, h16, x2, ln_w + (long)(l * 3 + 2) * Dd, ln_b + (long)(l * 3 + 2) * Dd);
    }

    // ---- output head ----
    hgemm(1, 2, 0, h16, wh + W_PROJW1, proj_b1, x2, M, HIDh, Dd, Dd, Dd, HIDh,
          zero, zero, zero, zero, zero, zero, 1, 1, 1.f);
    final_k<<<(Bb * Ls + 7) / 8, 256>>>(x2, proj_w2, proj_b2, basis, (float*)d_out);
}